// round 14
// baseline (speedup 1.0000x reference)
#include <cuda_runtime.h>
#include <cstdint>

// DynamicWeightAttention via mma.sync tf32, LN folded into the OPERAND:
//   staging stores x_hat = (x - mean)*rstd (tf32) -> h_d = dot + v_d exactly.
// Orientation: D[M,64] = Xhat[M,32] x W'[32,64], A = Xhat (smem), B = W'
// (32 regs/thread, PERSISTENT across tiles -> zero weight smem traffic).
// Warp = 16 rows x 32 dims; warp pair shares 16 rows, splits dims; partial
// scores exchanged via smem; pair-local named barriers (bar.sync, 64).
// TILE_M=64 rows/tile. Softmax over 16 consecutive rows = one group/warp-pair.

#define C_FEAT 32
#define HID    64
#define TILE_M 64
#define GRID_B 2048
#define XROW   36                 // padded words per row (conflict-free)

__device__ float  g_W[HID * C_FEAT];  // [d][k] = tf32(gamma[k]*w1[k][d])
__device__ float4 g_vw[HID / 2];      // {v_2j, w2_2j, v_2j+1, w2_2j+1}
__device__ float  g_b2;

__device__ __forceinline__ uint32_t tf32r(float x) {
    uint32_t r; asm("cvt.rna.tf32.f32 %0, %1;" : "=r"(r) : "f"(x)); return r;
}
__device__ __forceinline__ float tanha(float x) {
    float r; asm("tanh.approx.f32 %0, %1;" : "=f"(r) : "f"(x)); return r;
}
__device__ __forceinline__ void mma8(float& d0, float& d1, float& d2, float& d3,
                                     uint32_t a0, uint32_t a1, uint32_t a2, uint32_t a3,
                                     uint32_t b0, uint32_t b1) {
    asm("mma.sync.aligned.m16n8k8.row.col.f32.tf32.tf32.f32 "
        "{%0,%1,%2,%3}, {%4,%5,%6,%7}, {%8,%9}, {%0,%1,%2,%3};"
        : "+f"(d0), "+f"(d1), "+f"(d2), "+f"(d3)
        : "r"(a0), "r"(a1), "r"(a2), "r"(a3), "r"(b0), "r"(b1));
}
__device__ __forceinline__ void barp(int id) {
    asm volatile("bar.sync %0, 64;" :: "r"(id) : "memory");
}

__global__ void prep_kernel(const float* __restrict__ gamma, const float* __restrict__ beta,
                            const float* __restrict__ w1,    const float* __restrict__ b1,
                            const float* __restrict__ w2,    const float* __restrict__ b2) {
    int d = threadIdx.x;
    if (d >= HID) return;
    float v = 0.f;
    for (int k = 0; k < C_FEAT; k++) {
        g_W[d * C_FEAT + k] = __uint_as_float(tf32r(gamma[k] * w1[k * HID + d]));
        v += beta[k] * w1[k * HID + d];
    }
    v += b1[d];
    float* vw = (float*)&g_vw[d >> 1];
    vw[2 * (d & 1)]     = v;
    vw[2 * (d & 1) + 1] = w2[d];
    if (d == 0) g_b2 = b2[0];
}

__global__ __launch_bounds__(256, 3)
void dwa_kernel(const float* __restrict__ dyn, const float* __restrict__ stat,
                float* __restrict__ out, int tiles_per_block) {
    __shared__ uint32_t xs[TILE_M * XROW];            // 9 KB x-hat tile
    __shared__ __align__(16) float4 vws[HID / 2];     // 512 B {v,w2} pairs
    __shared__ float psum[2][TILE_M];                 // partial scores
    __shared__ float b2s;

    const int tid   = threadIdx.x;
    const int lane  = tid & 31;
    const int wid   = tid >> 5;
    const int g     = lane >> 2;      // groupID
    const int c     = lane & 3;       // threadID_in_group
    const int r     = tid >> 2;       // staged local row (0..63)
    const int q     = tid & 3;        // quarter: cols 4q..4q+3 of dyn AND stat
    const int pairI = wid >> 1;       // pair owns rows 16*pairI..+15 (= softmax grp)
    const int sub   = wid & 1;        // dim half: d in [32*sub, 32*sub+32)
    const int prow0 = pairI * 16;
    const int barid = 1 + pairI;

    if (tid < HID / 2) vws[tid] = g_vw[tid];
    if (tid == 0)      b2s = g_b2;

    // ---- B operand (weights) in registers, PERSISTENT across tiles ----
    // b0 = W'[k=8ks+c][d], b1 = W'[k=8ks+c+4][d], d = 32*sub + 8*nt + g
    uint32_t bw[4][4][2];
    #pragma unroll
    for (int ks = 0; ks < 4; ks++)
        #pragma unroll
        for (int nt = 0; nt < 4; nt++) {
            int d = 32 * sub + 8 * nt + g;
            bw[ks][nt][0] = __float_as_uint(g_W[d * C_FEAT + 8 * ks + c]);
            bw[ks][nt][1] = __float_as_uint(g_W[d * C_FEAT + 8 * ks + c + 4]);
        }
    __syncthreads();   // vws/b2s visible

    for (int it = 0; it < tiles_per_block; it++) {
        const long rbase = ((long)blockIdx.x * tiles_per_block + it) * TILE_M;
        const long grow  = rbase + r;

        // ---- stage quarter-row: 1 dyn float4 + 1 stat float4, coalesced ----
        float4 dv = ((const float4*)dyn)[grow * 4 + q];
        float4 sv = ((const float4*)stat)[(grow & 4095) * 4 + q];
        float s  = dv.x + dv.y + dv.z + dv.w + sv.x + sv.y + sv.z + sv.w;
        float ss = dv.x*dv.x + dv.y*dv.y + dv.z*dv.z + dv.w*dv.w
                 + sv.x*sv.x + sv.y*sv.y + sv.z*sv.z + sv.w*sv.w;
        s  += __shfl_xor_sync(0xffffffffu, s, 1);
        ss += __shfl_xor_sync(0xffffffffu, ss, 1);
        s  += __shfl_xor_sync(0xffffffffu, s, 2);
        ss += __shfl_xor_sync(0xffffffffu, ss, 2);
        const float mean = s * (1.0f / C_FEAT);
        const float var  = ss * (1.0f / C_FEAT) - mean * mean;
        const float rstd = rsqrtf(var + 1e-4f);

        // normalized tf32 x-hat; store word k at p=(k&3)*8+(k>>3)*2+((k>>2)&1):
        // dyn k=4q+j -> p=8j+q ; stat k=16+4q+j -> p=8j+4+q  (conflict-free)
        {
            uint32_t* xr = xs + r * XROW;
            float dxs[4] = {dv.x, dv.y, dv.z, dv.w};
            float sxs[4] = {sv.x, sv.y, sv.z, sv.w};
            #pragma unroll
            for (int j = 0; j < 4; j++) {
                xr[8 * j + q]     = tf32r((dxs[j] - mean) * rstd);
                xr[8 * j + 4 + q] = tf32r((sxs[j] - mean) * rstd);
            }
        }
        barp(barid);   // BAR1: pair's 16 rows staged

        // ---- A fragments: rows prow0+g, +8; words c*8..c*8+7 = 4 ks-frags ----
        const uint4* qlo = (const uint4*)(xs + (prow0 + g) * XROW + c * 8);
        const uint4* qhi = (const uint4*)(xs + (prow0 + g + 8) * XROW + c * 8);
        uint4 Alo0 = qlo[0], Alo1 = qlo[1];   // {ks0:a0,a2, ks1:a0,a2}, {ks2.., ks3..}
        uint4 Ahi0 = qhi[0], Ahi1 = qhi[1];   // same for a1,a3 (row g+8)

        float acc[4][4];
        #pragma unroll
        for (int nt = 0; nt < 4; nt++)
            #pragma unroll
            for (int z = 0; z < 4; z++) acc[nt][z] = 0.f;

        #pragma unroll
        for (int ks = 0; ks < 4; ks++) {
            uint4 Al = (ks < 2) ? Alo0 : Alo1;
            uint4 Ah = (ks < 2) ? Ahi0 : Ahi1;
            uint32_t a0 = (ks & 1) ? Al.z : Al.x;
            uint32_t a2 = (ks & 1) ? Al.w : Al.y;
            uint32_t a1 = (ks & 1) ? Ah.z : Ah.x;
            uint32_t a3 = (ks & 1) ? Ah.w : Ah.y;
            #pragma unroll
            for (int nt = 0; nt < 4; nt++)
                mma8(acc[nt][0], acc[nt][1], acc[nt][2], acc[nt][3],
                     a0, a1, a2, a3, bw[ks][nt][0], bw[ks][nt][1]);
        }

        // ---- epilogue: h = acc + v; sc += tanh(h)*w2 (LN already in operand) ----
        // thread: rows {g, g+8}, dims {32sub+8nt+2c, +1}; vw pair j=16sub+4nt+c
        float sc0 = 0.f, sc1 = 0.f;
        #pragma unroll
        for (int nt = 0; nt < 4; nt++) {
            float4 vw = vws[16 * sub + 4 * nt + c];   // {v0,w0,v1,w1}
            sc0 = fmaf(tanha(acc[nt][0] + vw.x), vw.y, sc0);
            sc0 = fmaf(tanha(acc[nt][1] + vw.z), vw.w, sc0);
            sc1 = fmaf(tanha(acc[nt][2] + vw.x), vw.y, sc1);
            sc1 = fmaf(tanha(acc[nt][3] + vw.z), vw.w, sc1);
        }
        // reduce over c-lanes (xor 1,2), publish per-sub partial
        sc0 += __shfl_xor_sync(0xffffffffu, sc0, 1);
        sc1 += __shfl_xor_sync(0xffffffffu, sc1, 1);
        sc0 += __shfl_xor_sync(0xffffffffu, sc0, 2);
        sc1 += __shfl_xor_sync(0xffffffffu, sc1, 2);
        if (c == 0) {
            psum[sub][prow0 + g]     = sc0;
            psum[sub][prow0 + 8 + g] = sc1;
        }
        barp(barid);   // BAR2: both dim-halves' partials visible

        // ---- finalize + softmax over the pair's 16 rows ----
        const float b2v = b2s;
        int r0 = prow0 + g;
        float scf0 = psum[0][r0]     + psum[1][r0]     + b2v;
        float scf1 = psum[0][r0 + 8] + psum[1][r0 + 8] + b2v;
        float m = fmaxf(scf0, scf1);
        m = fmaxf(m, __shfl_xor_sync(0xffffffffu, m, 4));
        m = fmaxf(m, __shfl_xor_sync(0xffffffffu, m, 8));
        m = fmaxf(m, __shfl_xor_sync(0xffffffffu, m, 16));
        float e0 = __expf(scf0 - m), e1 = __expf(scf1 - m);
        float es = e0 + e1;
        es += __shfl_xor_sync(0xffffffffu, es, 4);
        es += __shfl_xor_sync(0xffffffffu, es, 8);
        es += __shfl_xor_sync(0xffffffffu, es, 16);
        const float inv = 1.0f / es;

        if (c == 0) {   // sub 0 writes rows g, sub 1 writes rows g+8
            if (sub == 0) out[rbase + r0]     = e0 * inv;
            else          out[rbase + r0 + 8] = e1 * inv;
        }
    }
}

extern "C" void kernel_launch(void* const* d_in, const int* in_sizes, int n_in,
                              void* d_out, int out_size) {
    const float* dyn   = (const float*)d_in[0];
    const float* stat  = (const float*)d_in[1];
    const float* gamma = (const float*)d_in[2];
    const float* beta  = (const float*)d_in[3];
    const float* w1    = (const float*)d_in[4];
    const float* b1    = (const float*)d_in[5];
    const float* w2    = (const float*)d_in[6];
    const float* b2    = (const float*)d_in[7];
    float* out = (float*)d_out;

    const long nrows = (long)in_sizes[0] / 16;      // 4,194,304
    const long tiles = nrows / TILE_M;              // 65,536
    const int  tpb   = (int)(tiles / GRID_B);       // 32

    prep_kernel<<<1, 64>>>(gamma, beta, w1, b1, w2, b2);
    dwa_kernel<<<GRID_B, 256>>>(dyn, stat, out, tpb);
}

// round 16
// speedup vs baseline: 1.0027x; 1.0027x over previous
#include <cuda_runtime.h>
#include <cstdint>

// DynamicWeightAttention via mma.sync tf32, LN folded into the OPERAND:
//   staging stores x_hat = (x - mean)*rstd (tf32) -> h_d = dot + v_d exactly.
// Orientation: D[M,64] = Xhat[M,32] x W'[32,64], A = Xhat (smem), B = W'
// (32 regs/thread, PERSISTENT across tiles -> zero weight smem traffic).
// Warp = 16 rows x 32 dims; warp pair shares 16 rows, splits dims; partial
// scores exchanged via smem; pair-local named barriers (bar.sync, 64).
// TILE_M=64 rows/tile. Softmax over 16 consecutive rows = one group/warp-pair.

#define C_FEAT 32
#define HID    64
#define TILE_M 64
#define GRID_B 2048
#define XROW   36                 // padded words per row (conflict-free)

__device__ float  g_W[HID * C_FEAT];  // [d][k] = tf32(gamma[k]*w1[k][d])
__device__ float4 g_vw[HID / 2];      // {v_2j, w2_2j, v_2j+1, w2_2j+1}
__device__ float  g_b2;

__device__ __forceinline__ uint32_t tf32r(float x) {
    uint32_t r; asm("cvt.rna.tf32.f32 %0, %1;" : "=r"(r) : "f"(x)); return r;
}
__device__ __forceinline__ float tanha(float x) {
    float r; asm("tanh.approx.f32 %0, %1;" : "=f"(r) : "f"(x)); return r;
}
__device__ __forceinline__ void mma8(float& d0, float& d1, float& d2, float& d3,
                                     uint32_t a0, uint32_t a1, uint32_t a2, uint32_t a3,
                                     uint32_t b0, uint32_t b1) {
    asm("mma.sync.aligned.m16n8k8.row.col.f32.tf32.tf32.f32 "
        "{%0,%1,%2,%3}, {%4,%5,%6,%7}, {%8,%9}, {%0,%1,%2,%3};"
        : "+f"(d0), "+f"(d1), "+f"(d2), "+f"(d3)
        : "r"(a0), "r"(a1), "r"(a2), "r"(a3), "r"(b0), "r"(b1));
}
__device__ __forceinline__ void barp(int id) {
    asm volatile("bar.sync %0, 64;" :: "r"(id) : "memory");
}

__global__ void prep_kernel(const float* __restrict__ gamma, const float* __restrict__ beta,
                            const float* __restrict__ w1,    const float* __restrict__ b1,
                            const float* __restrict__ w2,    const float* __restrict__ b2) {
    int d = threadIdx.x;
    if (d >= HID) return;
    float v = 0.f;
    for (int k = 0; k < C_FEAT; k++) {
        g_W[d * C_FEAT + k] = __uint_as_float(tf32r(gamma[k] * w1[k * HID + d]));
        v += beta[k] * w1[k * HID + d];
    }
    v += b1[d];
    float* vw = (float*)&g_vw[d >> 1];
    vw[2 * (d & 1)]     = v;
    vw[2 * (d & 1) + 1] = w2[d];
    if (d == 0) g_b2 = b2[0];
}

__global__ __launch_bounds__(256, 3)
void dwa_kernel(const float* __restrict__ dyn, const float* __restrict__ stat,
                float* __restrict__ out, int tiles_per_block) {
    __shared__ uint32_t xs[TILE_M * XROW];            // 9 KB x-hat tile
    __shared__ __align__(16) float4 vws[HID / 2];     // 512 B {v,w2} pairs
    __shared__ float psum[2][TILE_M];                 // partial scores
    __shared__ float b2s;

    const int tid   = threadIdx.x;
    const int lane  = tid & 31;
    const int wid   = tid >> 5;
    const int g     = lane >> 2;      // groupID
    const int c     = lane & 3;       // threadID_in_group
    const int r     = tid >> 2;       // staged local row (0..63)
    const int q     = tid & 3;        // quarter: cols 4q..4q+3 of dyn AND stat
    const int pairI = wid >> 1;       // pair owns rows 16*pairI..+15 (= softmax grp)
    const int sub   = wid & 1;        // dim half: d in [32*sub, 32*sub+32)
    const int prow0 = pairI * 16;
    const int barid = 1 + pairI;

    if (tid < HID / 2) vws[tid] = g_vw[tid];
    if (tid == 0)      b2s = g_b2;

    // ---- B operand (weights) in registers, PERSISTENT across tiles ----
    // b0 = W'[k=8ks+c][d], b1 = W'[k=8ks+c+4][d], d = 32*sub + 8*nt + g
    uint32_t bw[4][4][2];
    #pragma unroll
    for (int ks = 0; ks < 4; ks++)
        #pragma unroll
        for (int nt = 0; nt < 4; nt++) {
            int d = 32 * sub + 8 * nt + g;
            bw[ks][nt][0] = __float_as_uint(g_W[d * C_FEAT + 8 * ks + c]);
            bw[ks][nt][1] = __float_as_uint(g_W[d * C_FEAT + 8 * ks + c + 4]);
        }
    __syncthreads();   // vws/b2s visible

    for (int it = 0; it < tiles_per_block; it++) {
        const long rbase = ((long)blockIdx.x * tiles_per_block + it) * TILE_M;
        const long grow  = rbase + r;

        // ---- stage quarter-row: 1 dyn float4 + 1 stat float4, coalesced ----
        float4 dv = ((const float4*)dyn)[grow * 4 + q];
        float4 sv = ((const float4*)stat)[(grow & 4095) * 4 + q];
        float s  = dv.x + dv.y + dv.z + dv.w + sv.x + sv.y + sv.z + sv.w;
        float ss = dv.x*dv.x + dv.y*dv.y + dv.z*dv.z + dv.w*dv.w
                 + sv.x*sv.x + sv.y*sv.y + sv.z*sv.z + sv.w*sv.w;
        s  += __shfl_xor_sync(0xffffffffu, s, 1);
        ss += __shfl_xor_sync(0xffffffffu, ss, 1);
        s  += __shfl_xor_sync(0xffffffffu, s, 2);
        ss += __shfl_xor_sync(0xffffffffu, ss, 2);
        const float mean = s * (1.0f / C_FEAT);
        const float var  = ss * (1.0f / C_FEAT) - mean * mean;
        const float rstd = rsqrtf(var + 1e-4f);

        // normalized tf32 x-hat; store word k at p=(k&3)*8+(k>>3)*2+((k>>2)&1):
        // dyn k=4q+j -> p=8j+q ; stat k=16+4q+j -> p=8j+4+q  (conflict-free)
        {
            uint32_t* xr = xs + r * XROW;
            float dxs[4] = {dv.x, dv.y, dv.z, dv.w};
            float sxs[4] = {sv.x, sv.y, sv.z, sv.w};
            #pragma unroll
            for (int j = 0; j < 4; j++) {
                xr[8 * j + q]     = tf32r((dxs[j] - mean) * rstd);
                xr[8 * j + 4 + q] = tf32r((sxs[j] - mean) * rstd);
            }
        }
        barp(barid);   // BAR1: pair's 16 rows staged

        // ---- A fragments: rows prow0+g, +8; words c*8..c*8+7 = 4 ks-frags ----
        const uint4* qlo = (const uint4*)(xs + (prow0 + g) * XROW + c * 8);
        const uint4* qhi = (const uint4*)(xs + (prow0 + g + 8) * XROW + c * 8);
        uint4 Alo0 = qlo[0], Alo1 = qlo[1];   // {ks0:a0,a2, ks1:a0,a2}, {ks2.., ks3..}
        uint4 Ahi0 = qhi[0], Ahi1 = qhi[1];   // same for a1,a3 (row g+8)

        float acc[4][4];
        #pragma unroll
        for (int nt = 0; nt < 4; nt++)
            #pragma unroll
            for (int z = 0; z < 4; z++) acc[nt][z] = 0.f;

        #pragma unroll
        for (int ks = 0; ks < 4; ks++) {
            uint4 Al = (ks < 2) ? Alo0 : Alo1;
            uint4 Ah = (ks < 2) ? Ahi0 : Ahi1;
            uint32_t a0 = (ks & 1) ? Al.z : Al.x;
            uint32_t a2 = (ks & 1) ? Al.w : Al.y;
            uint32_t a1 = (ks & 1) ? Ah.z : Ah.x;
            uint32_t a3 = (ks & 1) ? Ah.w : Ah.y;
            #pragma unroll
            for (int nt = 0; nt < 4; nt++)
                mma8(acc[nt][0], acc[nt][1], acc[nt][2], acc[nt][3],
                     a0, a1, a2, a3, bw[ks][nt][0], bw[ks][nt][1]);
        }

        // ---- epilogue: h = acc + v; sc += tanh(h)*w2 (LN already in operand) ----
        // thread: rows {g, g+8}, dims {32sub+8nt+2c, +1}; vw pair j=16sub+4nt+c
        float sc0 = 0.f, sc1 = 0.f;
        #pragma unroll
        for (int nt = 0; nt < 4; nt++) {
            float4 vw = vws[16 * sub + 4 * nt + c];   // {v0,w0,v1,w1}
            sc0 = fmaf(tanha(acc[nt][0] + vw.x), vw.y, sc0);
            sc0 = fmaf(tanha(acc[nt][1] + vw.z), vw.w, sc0);
            sc1 = fmaf(tanha(acc[nt][2] + vw.x), vw.y, sc1);
            sc1 = fmaf(tanha(acc[nt][3] + vw.z), vw.w, sc1);
        }
        // reduce over c-lanes (xor 1,2), publish per-sub partial
        sc0 += __shfl_xor_sync(0xffffffffu, sc0, 1);
        sc1 += __shfl_xor_sync(0xffffffffu, sc1, 1);
        sc0 += __shfl_xor_sync(0xffffffffu, sc0, 2);
        sc1 += __shfl_xor_sync(0xffffffffu, sc1, 2);
        if (c == 0) {
            psum[sub][prow0 + g]     = sc0;
            psum[sub][prow0 + 8 + g] = sc1;
        }
        barp(barid);   // BAR2: both dim-halves' partials visible

        // ---- finalize + softmax over the pair's 16 rows ----
        const float b2v = b2s;
        int r0 = prow0 + g;
        float scf0 = psum[0][r0]     + psum[1][r0]     + b2v;
        float scf1 = psum[0][r0 + 8] + psum[1][r0 + 8] + b2v;
        float m = fmaxf(scf0, scf1);
        m = fmaxf(m, __shfl_xor_sync(0xffffffffu, m, 4));
        m = fmaxf(m, __shfl_xor_sync(0xffffffffu, m, 8));
        m = fmaxf(m, __shfl_xor_sync(0xffffffffu, m, 16));
        float e0 = __expf(scf0 - m), e1 = __expf(scf1 - m);
        float es = e0 + e1;
        es += __shfl_xor_sync(0xffffffffu, es, 4);
        es += __shfl_xor_sync(0xffffffffu, es, 8);
        es += __shfl_xor_sync(0xffffffffu, es, 16);
        const float inv = 1.0f / es;

        if (c == 0) {   // sub 0 writes rows g, sub 1 writes rows g+8
            if (sub == 0) out[rbase + r0]     = e0 * inv;
            else          out[rbase + r0 + 8] = e1 * inv;
        }
    }
}

extern "C" void kernel_launch(void* const* d_in, const int* in_sizes, int n_in,
                              void* d_out, int out_size) {
    const float* dyn   = (const float*)d_in[0];
    const float* stat  = (const float*)d_in[1];
    const float* gamma = (const float*)d_in[2];
    const float* beta  = (const float*)d_in[3];
    const float* w1    = (const float*)d_in[4];
    const float* b1    = (const float*)d_in[5];
    const float* w2    = (const float*)d_in[6];
    const float* b2    = (const float*)d_in[7];
    float* out = (float*)d_out;

    const long nrows = (long)in_sizes[0] / 16;      // 4,194,304
    const long tiles = nrows / TILE_M;              // 65,536
    const int  tpb   = (int)(tiles / GRID_B);       // 32

    prep_kernel<<<1, 64>>>(gamma, beta, w1, b1, w2, b2);
    dwa_kernel<<<GRID_B, 256>>>(dyn, stat, out, tpb);
}